// round 17
// baseline (speedup 1.0000x reference)
#include <cuda_runtime.h>
#include <cstdint>

// Problem constants (fixed shapes per reference setup_inputs)
#define S 8192      // tokens
#define M 2048      // model dim
#define E 64        // experts
#define CAP 256     // capacity = TOP_K * ceil(S/E) = 2 * 128
#define BM 32       // tokens per gemm block
#define BKT 32      // k per tile
#define NTK (M / BKT)   // 64 k-tiles
#define NG (S / BM)     // 256 gemm blocks, full-K each (no partials)
#define FILL_F4_PER_BLOCK 8192

typedef unsigned long long ull;

// ---- device scratch (no allocations allowed; zero-initialized at load) ----
__device__ int   g_expert[S];
__device__ float g_gate[S];
__device__ int   g_cnt[3];              // [1]=soft(gemm blocks), [2]=fill
__device__ int   g_rank_pass;           // rank blocks past their waits

__device__ __forceinline__ ull dup2(float x) {
    ull r; asm("mov.b64 %0, {%1, %1};" : "=l"(r) : "f"(x)); return r;
}
__device__ __forceinline__ void ffma2(ull &acc, ull a, ull b) {
    asm("fma.rn.f32x2 %0, %1, %2, %0;" : "+l"(acc) : "l"(a), "l"(b));
}
__device__ __forceinline__ float2 unpack2(ull v) {
    float2 f; asm("mov.b64 {%0, %1}, %2;" : "=f"(f.x), "=f"(f.y) : "l"(v));
    return f;
}

// Release: all block stores visible, then bump counter.
__device__ __forceinline__ void block_signal(int* c) {
    __syncthreads();
    __threadfence();
    if (threadIdx.x == 0) atomicAdd(c, 1);
}
// Acquire: spin until counter reaches target.
__device__ __forceinline__ void block_wait(int* c, int target) {
    if (threadIdx.x == 0) {
        volatile int* v = c;
        while (*v < target) __nanosleep(128);
    }
    __syncthreads();
    __threadfence();
}

// ============================================================
// Fused pipeline kernel (self-resetting). Grid layout:
//   [0, NG)                 : GEMM blocks — 32 tokens x 64 experts,
//                             FULL K per block, tiny 8-reg accum,
//                             inline softargmax from smem logits.
//                             Natural regs target: <=48 -> 5+ blocks/SM
//                             so fill gets 40+ warps/SM.
//   [NG, NG+nfill)          : pure zero-fill blocks
//   [NG+nfill, NG+nfill+E)  : rank blocks — scan after soft,
//                             scatter after fill; e==0 resets counters.
// ============================================================
__global__ void __launch_bounds__(256) fused_kernel(const float* __restrict__ A,
                                                    const float* __restrict__ B,
                                                    float4* __restrict__ out4,
                                                    float* __restrict__ outF,
                                                    int nfill, int two) {
    const int bx  = blockIdx.x;
    const int tid = threadIdx.x;

    if (bx >= NG) {
        if (bx < NG + nfill) {
            // ---------------- pure fill branch ----------------
            const int fb = bx - NG;
            int idx = fb * FILL_F4_PER_BLOCK + tid;
            const float4 z = make_float4(0.f, 0.f, 0.f, 0.f);
            #pragma unroll 8
            for (int i = 0; i < FILL_F4_PER_BLOCK / 256; i++) {
                __stcs(&out4[idx], z);
                idx += 256;
            }
            block_signal(&g_cnt[2]);
            return;
        }
        // ---------------- rank branch ----------------
        const int e = bx - NG - nfill;
        block_wait(&g_cnt[1], NG);   // all gemm blocks' soft results ready

        // Early scan (overlaps remaining fill): positions packed 16-bit.
        __shared__ int warp_sums[8];
        const int lane = tid & 31;
        const int warp = tid >> 5;
        unsigned flags = 0;
        int posp[16];
        int running = 0;
        #pragma unroll
        for (int pass = 0; pass < 2; pass++) {
            int ex[16];
            #pragma unroll
            for (int j = 0; j < 16; j++)
                ex[j] = __ldcg(&g_expert[(pass * 16 + j) * 256 + tid]);
            #pragma unroll
            for (int j = 0; j < 16; j++) {
                const int c = pass * 16 + j;
                int flag = (ex[j] == e) ? 1 : 0;
                unsigned bits = __ballot_sync(0xffffffffu, flag);
                int excl = __popc(bits & ((1u << lane) - 1u));
                if (lane == 0) warp_sums[warp] = __popc(bits);
                __syncthreads();
                int woff = 0, tot = 0;
                #pragma unroll
                for (int w = 0; w < 8; w++) {
                    int ws = warp_sums[w];
                    if (w < warp) woff += ws;
                    tot += ws;
                }
                int pos = running + woff + excl;
                flags |= ((unsigned)flag) << c;
                if (c & 1) posp[c >> 1] |= (pos & 0xffff) << 16;
                else       posp[c >> 1]  = (pos & 0xffff);
                running += tot;
                __syncthreads();
            }
        }

        block_wait(&g_cnt[2], nfill);   // output fully zeroed

        // Scatter-only tail (~128 tokens per expert).
        #pragma unroll
        for (int c = 0; c < 32; c++) {
            int pos = (posp[c >> 1] >> ((c & 1) * 16)) & 0xffff;
            if (((flags >> c) & 1u) && pos < CAP) {
                int s = c * 256 + tid;
                size_t off = (size_t)s * (E * CAP) + (size_t)e * CAP + (size_t)pos;
                outF[off] = __ldcg(&g_gate[s]);
                if (two) outF[(size_t)S * E * CAP + off] = 1.0f;
            }
        }

        // Self-reset for the next graph replay.
        block_signal(&g_rank_pass);
        if (e == 0) {
            if (tid == 0) {
                volatile int* v = &g_rank_pass;
                while (*v < E) __nanosleep(128);
            }
            __syncthreads();
            if (tid == 0) {
                g_cnt[1] = 0; g_cnt[2] = 0; g_rank_pass = 0;
                __threadfence();
            }
        }
        return;
    }

    // ---------------- gemm branch: 32 tok x 64 exp, full K ----------------
    __shared__ __align__(16) float As[BKT][BM];       // [k][token] 4 KB
    __shared__ __align__(16) ull   Bs[2][BKT][32];    // dup'd {b,b} 16 KB
    __shared__ float logits[BM][66];                  // 8.25 KB

    const int tokBase = bx * BM;

    // A loader: one float4/thread/tile: token = tid&31, kq = tid>>5 (0..7)
    const int atok = tid & 31;
    const int akq  = tid >> 5;
    const float* arow = A + (size_t)(tokBase + atok) * M + akq * 4;

    // B loader: two float4/thread/tile: expert = tid>>2, kq = tid&3 and +4
    const int be = tid >> 2;
    const int bj = tid & 3;
    const float* brow = B + (size_t)be * M + bj * 4;
    const int bp   = (be >> 1) & 1;             // plane
    const int bslt = (be >> 2) * 2 + (be & 1);  // ull slot within row

    // compute roles: token pair tt (tokens 2tt, 2tt+1), experts te*4..+3
    const int tt = tid >> 4;          // 0..15
    const int te = tid & 15;          // 0..15

    ull acc[4] = {0ull, 0ull, 0ull, 0ull};

    // register-prefetch double buffering
    float4 av  = *(const float4*)(arow);
    float4 bv0 = *(const float4*)(brow);
    float4 bv1 = *(const float4*)(brow + 16);

    for (int tile = 0; tile < NTK; tile++) {
        __syncthreads();  // previous compute done before overwrite

        As[akq*4 + 0][atok] = av.x;  As[akq*4 + 1][atok] = av.y;
        As[akq*4 + 2][atok] = av.z;  As[akq*4 + 3][atok] = av.w;

        Bs[bp][bj*4 + 0][bslt] = dup2(bv0.x);
        Bs[bp][bj*4 + 1][bslt] = dup2(bv0.y);
        Bs[bp][bj*4 + 2][bslt] = dup2(bv0.z);
        Bs[bp][bj*4 + 3][bslt] = dup2(bv0.w);
        Bs[bp][16 + bj*4 + 0][bslt] = dup2(bv1.x);
        Bs[bp][16 + bj*4 + 1][bslt] = dup2(bv1.y);
        Bs[bp][16 + bj*4 + 2][bslt] = dup2(bv1.z);
        Bs[bp][16 + bj*4 + 3][bslt] = dup2(bv1.w);

        __syncthreads();

        if (tile + 1 < NTK) {  // prefetch next tile while computing
            const int kb = (tile + 1) * BKT;
            av  = *(const float4*)(arow + kb);
            bv0 = *(const float4*)(brow + kb);
            bv1 = *(const float4*)(brow + kb + 16);
        }

        #pragma unroll
        for (int kk = 0; kk < BKT; kk++) {
            ull a = *(const ull*)&As[kk][tt * 2];                   // {t0,t1}
            ulonglong2 b0 = ((const ulonglong2*)&Bs[0][kk][0])[te]; // e,e+1
            ulonglong2 b1 = ((const ulonglong2*)&Bs[1][kk][0])[te]; // e+2,e+3
            ffma2(acc[0], a, b0.x);
            ffma2(acc[1], a, b0.y);
            ffma2(acc[2], a, b1.x);
            ffma2(acc[3], a, b1.y);
        }
    }

    // Stage logits in smem: tokens 2tt,2tt+1 x experts te*4..+3
    #pragma unroll
    for (int j = 0; j < 4; j++) {
        float2 v = unpack2(acc[j]);
        logits[tt*2    ][te*4 + j] = v.x;
        logits[tt*2 + 1][te*4 + j] = v.y;
    }
    __syncthreads();

    // Inline softargmax: warp w handles tokens 4w..4w+3.
    {
        const int warp = tid >> 5;
        const int lane = tid & 31;
        #pragma unroll
        for (int i = 0; i < 4; i++) {
            int tl = warp * 4 + i;
            float v0 = logits[tl][lane];
            float v1 = logits[tl][lane + 32];
            float bvv; int bi;
            if (v0 >= v1) { bvv = v0; bi = lane; }
            else          { bvv = v1; bi = lane + 32; }
            #pragma unroll
            for (int off = 16; off; off >>= 1) {
                float ov = __shfl_xor_sync(0xffffffffu, bvv, off);
                int   oi = __shfl_xor_sync(0xffffffffu, bi, off);
                if (ov > bvv || (ov == bvv && oi < bi)) { bvv = ov; bi = oi; }
            }
            float ssum = expf(v0 - bvv) + expf(v1 - bvv);
            #pragma unroll
            for (int off = 16; off; off >>= 1)
                ssum += __shfl_xor_sync(0xffffffffu, ssum, off);
            if (lane == 0) {
                g_expert[tokBase + tl] = bi;
                g_gate[tokBase + tl]   = 1.0f / ssum;
            }
        }
    }
    block_signal(&g_cnt[1]);
}

// ============================================================
extern "C" void kernel_launch(void* const* d_in, const int* in_sizes, int n_in,
                              void* d_out, int out_size) {
    const float* inp = (const float*)d_in[0];   // [S, M]
    const float* wg  = (const float*)d_in[1];   // [E, M]
    float* out = (float*)d_out;

    const long long SEC = (long long)S * E * CAP;
    const int two = ((long long)out_size >= 2 * SEC) ? 1 : 0;

    const int nf4   = out_size / 4;
    const int nfill = nf4 / FILL_F4_PER_BLOCK;   // divides exactly for both sizes

    fused_kernel<<<NG + nfill + E, 256>>>(inp, wg, (float4*)out, out, nfill, two);
}